// round 1
// baseline (speedup 1.0000x reference)
#include <cuda_runtime.h>
#include <cstdint>

#define NMAX   100000
#define CDIM   50
#define HIDD   256
#define INDIM  500
#define KHOP   10

// ---------------- static scratch (no allocations allowed) ----------------
static __device__ float g_x1[(size_t)NMAX * HIDD];                 // MLP hidden
static __device__ float g_H [(size_t)(KHOP + 1) * NMAX * CDIM];    // hop results
static __device__ float g_norm[NMAX];
static __device__ int   g_deg [NMAX];

// ---------------- generic tiled fp32 GEMM: C = op(A@B + bias) ----------------
// A: [M,K] row-major, B: [K,N] row-major, C: [M,N] row-major. 256 threads.
template <int BM, int BN, int BK, int TM, int TN, bool RELU>
__global__ void sgemm_bias(const float* __restrict__ A,
                           const float* __restrict__ B,
                           const float* __restrict__ bias,
                           float* __restrict__ C,
                           int M, int N, int K) {
    __shared__ float As[BK][BM];
    __shared__ float Bs[BK][BN];

    const int tid = threadIdx.x;                 // 0..255
    const int tx  = tid % (BN / TN);
    const int ty  = tid / (BN / TN);
    const int row0 = blockIdx.y * BM;
    const int col0 = blockIdx.x * BN;

    float acc[TM][TN];
#pragma unroll
    for (int i = 0; i < TM; i++)
#pragma unroll
        for (int j = 0; j < TN; j++) acc[i][j] = 0.f;

    for (int kt = 0; kt < K; kt += BK) {
        // load A tile (transposed into smem)
#pragma unroll 4
        for (int idx = tid; idx < BM * BK; idx += 256) {
            int m = idx / BK, k = idx % BK;
            int gr = row0 + m, gk = kt + k;
            As[k][m] = (gr < M && gk < K) ? A[(size_t)gr * K + gk] : 0.f;
        }
        // load B tile
#pragma unroll 4
        for (int idx = tid; idx < BK * BN; idx += 256) {
            int k = idx / BN, n = idx % BN;
            int gk = kt + k, gc = col0 + n;
            Bs[k][n] = (gk < K && gc < N) ? B[(size_t)gk * N + gc] : 0.f;
        }
        __syncthreads();

#pragma unroll
        for (int kk = 0; kk < BK; kk++) {
            float aF[TM], bF[TN];
#pragma unroll
            for (int i = 0; i < TM; i++) aF[i] = As[kk][ty * TM + i];
#pragma unroll
            for (int j = 0; j < TN; j++) bF[j] = Bs[kk][tx * TN + j];
#pragma unroll
            for (int i = 0; i < TM; i++)
#pragma unroll
                for (int j = 0; j < TN; j++) acc[i][j] += aF[i] * bF[j];
        }
        __syncthreads();
    }

#pragma unroll
    for (int i = 0; i < TM; i++) {
        int gr = row0 + ty * TM + i;
        if (gr >= M) continue;
#pragma unroll
        for (int j = 0; j < TN; j++) {
            int gc = col0 + tx * TN + j;
            if (gc >= N) continue;
            float v = acc[i][j] + bias[gc];
            if (RELU) v = fmaxf(v, 0.f);
            C[(size_t)gr * N + gc] = v;
        }
    }
}

// ---------------- small helpers ----------------
__global__ void zero_f_kernel(float* __restrict__ p, int n) {
    int i = blockIdx.x * blockDim.x + threadIdx.x;
    if (i < n) p[i] = 0.f;
}

__global__ void zero_i_kernel(int* __restrict__ p, int n) {
    int i = blockIdx.x * blockDim.x + threadIdx.x;
    if (i < n) p[i] = 0;
}

__global__ void hist_kernel(const int* __restrict__ dst, int* __restrict__ deg, int E) {
    int i = blockIdx.x * blockDim.x + threadIdx.x;
    if (i < E) atomicAdd(&deg[dst[i]], 1);
}

__global__ void norm_kernel(const int* __restrict__ deg, float* __restrict__ nrm, int n) {
    int i = blockIdx.x * blockDim.x + threadIdx.x;
    if (i < n) nrm[i] = rsqrtf((float)deg[i]);
}

// one thread per (edge, float2-column). val = norm[src] * h_in[src]; red into h_out[dst].
__global__ void scatter_kernel(const int* __restrict__ src, const int* __restrict__ dst,
                               const float* __restrict__ nrm,
                               const float* __restrict__ hin, float* __restrict__ hout,
                               int E) {
    int t = blockIdx.x * blockDim.x + threadIdx.x;
    int e = t / (CDIM / 2);
    int p = t - e * (CDIM / 2);
    if (e >= E) return;
    int s = src[e];
    int d = dst[e];
    float ns = nrm[s];
    const float2 hv = *reinterpret_cast<const float2*>(hin + (size_t)s * CDIM + p * 2);
    float vx = hv.x * ns, vy = hv.y * ns;
    float* addr = hout + (size_t)d * CDIM + p * 2;
    asm volatile("red.global.add.v2.f32 [%0], {%1, %2};"
                 :: "l"(addr), "f"(vx), "f"(vy) : "memory");
}

__global__ void scale_kernel(float* __restrict__ h, const float* __restrict__ nrm, int total) {
    int i = blockIdx.x * blockDim.x + threadIdx.x;
    if (i < total) h[i] *= nrm[i / CDIM];
}

// one warp per node: S_k = sigmoid(<H[n,k,:], s>), out[n,:] = sum_k S_k * H[n,k,:]
__global__ void final_kernel(const float* __restrict__ H, const float* __restrict__ s,
                             float* __restrict__ out, int N) {
    int t = blockIdx.x * blockDim.x + threadIdx.x;
    int n = t >> 5;
    int lane = t & 31;
    if (n >= N) return;

    const bool hi = (lane < CDIM - 32);
    float s0 = s[lane];
    float s1 = hi ? s[lane + 32] : 0.f;

    float acc0 = 0.f, acc1 = 0.f;
    size_t plane = (size_t)N * CDIM;
    const float* base = H + (size_t)n * CDIM;

#pragma unroll
    for (int k = 0; k <= KHOP; k++) {
        const float* r = base + (size_t)k * plane;
        float h0 = r[lane];
        float h1 = hi ? r[lane + 32] : 0.f;
        float dot = h0 * s0 + h1 * s1;
#pragma unroll
        for (int off = 16; off; off >>= 1)
            dot += __shfl_xor_sync(0xffffffffu, dot, off);
        float S = 1.f / (1.f + __expf(-dot));
        acc0 += S * h0;
        acc1 += S * h1;
    }
    out[(size_t)n * CDIM + lane] = acc0;
    if (hi) out[(size_t)n * CDIM + lane + 32] = acc1;
}

// ---------------- launch ----------------
extern "C" void kernel_launch(void* const* d_in, const int* in_sizes, int n_in,
                              void* d_out, int out_size) {
    const float* feats = (const float*)d_in[0];   // [N, 500]
    const float* W1    = (const float*)d_in[1];   // [500, 256]
    const float* b1    = (const float*)d_in[2];   // [256]
    const float* W2    = (const float*)d_in[3];   // [256, 50]
    const float* b2    = (const float*)d_in[4];   // [50]
    const float* svec  = (const float*)d_in[5];   // [50, 1]
    const int*   src   = (const int*)d_in[6];     // [E]
    const int*   dst   = (const int*)d_in[7];     // [E]
    float* out = (float*)d_out;

    const int N = in_sizes[0] / INDIM;            // 100000
    const int E = in_sizes[6];                    // 1600000

    void *pv;
    cudaGetSymbolAddress(&pv, g_x1);   float* x1   = (float*)pv;
    cudaGetSymbolAddress(&pv, g_H);    float* H    = (float*)pv;
    cudaGetSymbolAddress(&pv, g_norm); float* nrm  = (float*)pv;
    cudaGetSymbolAddress(&pv, g_deg);  int*   deg  = (int*)pv;

    const size_t plane = (size_t)N * CDIM;

    // 1) MLP layer 1: x1 = relu(feats @ W1 + b1)
    {
        dim3 grid((HIDD + 127) / 128, (N + 127) / 128);
        sgemm_bias<128, 128, 8, 8, 8, true><<<grid, 256>>>(feats, W1, b1, x1, N, HIDD, INDIM);
    }
    // 2) MLP layer 2: H[0] = x1 @ W2 + b2
    {
        dim3 grid((CDIM + 63) / 64, (N + 127) / 128);
        sgemm_bias<128, 64, 16, 8, 4, false><<<grid, 256>>>(x1, W2, b2, H, N, CDIM, HIDD);
    }
    // 3) degrees -> norm = deg^-1/2
    zero_i_kernel<<<(N + 255) / 256, 256>>>(deg, N);
    hist_kernel<<<(E + 255) / 256, 256>>>(dst, deg, E);
    norm_kernel<<<(N + 255) / 256, 256>>>(deg, nrm, N);

    // 4) K propagation hops
    const int scat_threads = E * (CDIM / 2);
    for (int k = 1; k <= KHOP; k++) {
        float* hin  = H + (size_t)(k - 1) * plane;
        float* hout = H + (size_t)k * plane;
        zero_f_kernel<<<(int)((plane + 255) / 256), 256>>>(hout, (int)plane);
        scatter_kernel<<<(scat_threads + 255) / 256, 256>>>(src, dst, nrm, hin, hout, E);
        scale_kernel<<<(int)((plane + 255) / 256), 256>>>(hout, nrm, (int)plane);
    }

    // 5) sigmoid-gated combine
    final_kernel<<<(N * 32 + 255) / 256, 256>>>(H, svec, out, N);
}

// round 2
// speedup vs baseline: 1.4443x; 1.4443x over previous
#include <cuda_runtime.h>
#include <cstdint>

#define NMAX   100000
#define EMAX   1600000
#define CDIM   50
#define HIDD   256
#define INDIM  500
#define KHOP   10

// ---------------- static scratch (no allocations allowed) ----------------
static __device__ float g_x1[(size_t)NMAX * HIDD];                 // MLP hidden
static __device__ float g_H [(size_t)(KHOP + 1) * NMAX * CDIM];    // hop results
static __device__ float g_norm[NMAX];
static __device__ int   g_deg   [NMAX];
static __device__ int   g_rowptr[NMAX + 1];
static __device__ int   g_cursor[NMAX];
static __device__ int   g_bsum  [1024];
static __device__ int   g_col   [EMAX];

// ---------------- generic tiled fp32 GEMM: C = op(A@B + bias) ----------------
template <int BM, int BN, int BK, int TM, int TN, bool RELU>
__global__ void sgemm_bias(const float* __restrict__ A,
                           const float* __restrict__ B,
                           const float* __restrict__ bias,
                           float* __restrict__ C,
                           int M, int N, int K) {
    __shared__ float As[BK][BM];
    __shared__ float Bs[BK][BN];

    const int tid = threadIdx.x;                 // 0..255
    const int tx  = tid % (BN / TN);
    const int ty  = tid / (BN / TN);
    const int row0 = blockIdx.y * BM;
    const int col0 = blockIdx.x * BN;

    float acc[TM][TN];
#pragma unroll
    for (int i = 0; i < TM; i++)
#pragma unroll
        for (int j = 0; j < TN; j++) acc[i][j] = 0.f;

    for (int kt = 0; kt < K; kt += BK) {
#pragma unroll 4
        for (int idx = tid; idx < BM * BK; idx += 256) {
            int m = idx / BK, k = idx % BK;
            int gr = row0 + m, gk = kt + k;
            As[k][m] = (gr < M && gk < K) ? A[(size_t)gr * K + gk] : 0.f;
        }
#pragma unroll 4
        for (int idx = tid; idx < BK * BN; idx += 256) {
            int k = idx / BN, n = idx % BN;
            int gk = kt + k, gc = col0 + n;
            Bs[k][n] = (gk < K && gc < N) ? B[(size_t)gk * N + gc] : 0.f;
        }
        __syncthreads();

#pragma unroll
        for (int kk = 0; kk < BK; kk++) {
            float aF[TM], bF[TN];
#pragma unroll
            for (int i = 0; i < TM; i++) aF[i] = As[kk][ty * TM + i];
#pragma unroll
            for (int j = 0; j < TN; j++) bF[j] = Bs[kk][tx * TN + j];
#pragma unroll
            for (int i = 0; i < TM; i++)
#pragma unroll
                for (int j = 0; j < TN; j++) acc[i][j] += aF[i] * bF[j];
        }
        __syncthreads();
    }

#pragma unroll
    for (int i = 0; i < TM; i++) {
        int gr = row0 + ty * TM + i;
        if (gr >= M) continue;
#pragma unroll
        for (int j = 0; j < TN; j++) {
            int gc = col0 + tx * TN + j;
            if (gc >= N) continue;
            float v = acc[i][j] + bias[gc];
            if (RELU) v = fmaxf(v, 0.f);
            C[(size_t)gr * N + gc] = v;
        }
    }
}

// ---------------- CSR build helpers ----------------
__global__ void zero_i_kernel(int* __restrict__ p, int n) {
    int i = blockIdx.x * blockDim.x + threadIdx.x;
    if (i < n) p[i] = 0;
}

__global__ void hist_kernel(const int* __restrict__ dst, int* __restrict__ deg, int E) {
    int i = blockIdx.x * blockDim.x + threadIdx.x;
    if (i < E) atomicAdd(&deg[dst[i]], 1);
}

__global__ void norm_kernel(const int* __restrict__ deg, float* __restrict__ nrm, int n) {
    int i = blockIdx.x * blockDim.x + threadIdx.x;
    if (i < n) nrm[i] = rsqrtf((float)deg[i]);
}

// Phase 1: per-block exclusive scan of deg -> rowptr (local), block totals -> bsum
__global__ void scan_block(const int* __restrict__ deg, int* __restrict__ rowptr,
                           int* __restrict__ bsum, int n) {
    __shared__ int sh[512];
    int tid = threadIdx.x;
    int gid = blockIdx.x * 512 + tid;
    int v = (gid < n) ? deg[gid] : 0;
    sh[tid] = v;
    __syncthreads();
    // Hillis-Steele inclusive scan
    for (int off = 1; off < 512; off <<= 1) {
        int t = (tid >= off) ? sh[tid - off] : 0;
        __syncthreads();
        sh[tid] += t;
        __syncthreads();
    }
    if (gid < n) rowptr[gid] = sh[tid] - v;       // exclusive
    if (tid == 511) bsum[blockIdx.x] = sh[511];   // block total
}

// Phase 2: single block exclusive scan of block sums
__global__ void scan_sums(int* __restrict__ bsum, int nb) {
    __shared__ int sh[1024];
    int tid = threadIdx.x;
    int v = (tid < nb) ? bsum[tid] : 0;
    sh[tid] = v;
    __syncthreads();
    for (int off = 1; off < 1024; off <<= 1) {
        int t = (tid >= off) ? sh[tid - off] : 0;
        __syncthreads();
        sh[tid] += t;
        __syncthreads();
    }
    if (tid < nb) bsum[tid] = sh[tid] - v;        // exclusive
}

// Phase 3: add block offsets; init cursor; set rowptr[n] = E
__global__ void scan_finish(int* __restrict__ rowptr, const int* __restrict__ bsum,
                            int* __restrict__ cursor, int n, int E) {
    int gid = blockIdx.x * blockDim.x + threadIdx.x;
    if (gid < n) {
        int r = rowptr[gid] + bsum[gid / 512];
        rowptr[gid] = r;
        cursor[gid] = r;
    }
    if (gid == 0) rowptr[n] = E;
}

__global__ void fill_kernel(const int* __restrict__ src, const int* __restrict__ dst,
                            int* __restrict__ cursor, int* __restrict__ col, int E) {
    int e = blockIdx.x * blockDim.x + threadIdx.x;
    if (e >= E) return;
    int pos = atomicAdd(&cursor[dst[e]], 1);
    col[pos] = src[e];
}

// ---------------- fused pull-gather hop ----------------
// warp per node: h_out[d,:] = norm[d] * sum_{s in N(d)} norm[s] * h_in[s,:]
__global__ void spmm_pull(const int* __restrict__ rowptr, const int* __restrict__ col,
                          const float* __restrict__ nrm,
                          const float* __restrict__ hin, float* __restrict__ hout,
                          int N) {
    int t = blockIdx.x * blockDim.x + threadIdx.x;
    int n = t >> 5;
    int lane = t & 31;
    if (n >= N) return;

    int beg = rowptr[n];
    int end = rowptr[n + 1];
    const bool hi = (lane < CDIM - 32);

    float acc0 = 0.f, acc1 = 0.f;
    int j = beg;
    for (; j + 1 < end; j += 2) {
        int s0 = col[j], s1 = col[j + 1];
        float n0 = nrm[s0], n1 = nrm[s1];
        const float* r0 = hin + (size_t)s0 * CDIM;
        const float* r1 = hin + (size_t)s1 * CDIM;
        float a0 = r0[lane];
        float a1 = r1[lane];
        float b0 = hi ? r0[lane + 32] : 0.f;
        float b1 = hi ? r1[lane + 32] : 0.f;
        acc0 += n0 * a0 + n1 * a1;
        acc1 += n0 * b0 + n1 * b1;
    }
    if (j < end) {
        int s0 = col[j];
        float n0 = nrm[s0];
        const float* r0 = hin + (size_t)s0 * CDIM;
        acc0 += n0 * r0[lane];
        if (hi) acc1 += n0 * r0[lane + 32];
    }

    float nd = nrm[n];
    hout[(size_t)n * CDIM + lane] = nd * acc0;
    if (hi) hout[(size_t)n * CDIM + lane + 32] = nd * acc1;
}

// ---------------- final sigmoid-gated combine ----------------
__global__ void final_kernel(const float* __restrict__ H, const float* __restrict__ s,
                             float* __restrict__ out, int N) {
    int t = blockIdx.x * blockDim.x + threadIdx.x;
    int n = t >> 5;
    int lane = t & 31;
    if (n >= N) return;

    const bool hi = (lane < CDIM - 32);
    float s0 = s[lane];
    float s1 = hi ? s[lane + 32] : 0.f;

    float acc0 = 0.f, acc1 = 0.f;
    size_t plane = (size_t)N * CDIM;
    const float* base = H + (size_t)n * CDIM;

#pragma unroll
    for (int k = 0; k <= KHOP; k++) {
        const float* r = base + (size_t)k * plane;
        float h0 = r[lane];
        float h1 = hi ? r[lane + 32] : 0.f;
        float dot = h0 * s0 + h1 * s1;
#pragma unroll
        for (int off = 16; off; off >>= 1)
            dot += __shfl_xor_sync(0xffffffffu, dot, off);
        float S = 1.f / (1.f + __expf(-dot));
        acc0 += S * h0;
        acc1 += S * h1;
    }
    out[(size_t)n * CDIM + lane] = acc0;
    if (hi) out[(size_t)n * CDIM + lane + 32] = acc1;
}

// ---------------- launch ----------------
extern "C" void kernel_launch(void* const* d_in, const int* in_sizes, int n_in,
                              void* d_out, int out_size) {
    const float* feats = (const float*)d_in[0];   // [N, 500]
    const float* W1    = (const float*)d_in[1];   // [500, 256]
    const float* b1    = (const float*)d_in[2];   // [256]
    const float* W2    = (const float*)d_in[3];   // [256, 50]
    const float* b2    = (const float*)d_in[4];   // [50]
    const float* svec  = (const float*)d_in[5];   // [50, 1]
    const int*   src   = (const int*)d_in[6];     // [E]
    const int*   dst   = (const int*)d_in[7];     // [E]
    float* out = (float*)d_out;

    const int N = in_sizes[0] / INDIM;            // 100000
    const int E = in_sizes[6];                    // 1600000

    void *pv;
    cudaGetSymbolAddress(&pv, g_x1);     float* x1     = (float*)pv;
    cudaGetSymbolAddress(&pv, g_H);      float* H      = (float*)pv;
    cudaGetSymbolAddress(&pv, g_norm);   float* nrm    = (float*)pv;
    cudaGetSymbolAddress(&pv, g_deg);    int*   deg    = (int*)pv;
    cudaGetSymbolAddress(&pv, g_rowptr); int*   rowptr = (int*)pv;
    cudaGetSymbolAddress(&pv, g_cursor); int*   cursor = (int*)pv;
    cudaGetSymbolAddress(&pv, g_bsum);   int*   bsum   = (int*)pv;
    cudaGetSymbolAddress(&pv, g_col);    int*   col    = (int*)pv;

    const size_t plane = (size_t)N * CDIM;
    const int nb = (N + 511) / 512;               // scan blocks (196)

    // 1) MLP layer 1: x1 = relu(feats @ W1 + b1)
    {
        dim3 grid((HIDD + 127) / 128, (N + 127) / 128);
        sgemm_bias<128, 128, 8, 8, 8, true><<<grid, 256>>>(feats, W1, b1, x1, N, HIDD, INDIM);
    }
    // 2) MLP layer 2: H[0] = x1 @ W2 + b2
    {
        dim3 grid((CDIM + 63) / 64, (N + 127) / 128);
        sgemm_bias<128, 64, 16, 8, 4, false><<<grid, 256>>>(x1, W2, b2, H, N, CDIM, HIDD);
    }
    // 3) CSR build: degrees -> norm, rowptr (scan), col (fill)
    zero_i_kernel<<<(N + 255) / 256, 256>>>(deg, N);
    hist_kernel<<<(E + 255) / 256, 256>>>(dst, deg, E);
    norm_kernel<<<(N + 255) / 256, 256>>>(deg, nrm, N);
    scan_block<<<nb, 512>>>(deg, rowptr, bsum, N);
    scan_sums<<<1, 1024>>>(bsum, nb);
    scan_finish<<<(N + 255) / 256, 256>>>(rowptr, bsum, cursor, N, E);
    fill_kernel<<<(E + 255) / 256, 256>>>(src, dst, cursor, col, E);

    // 4) K propagation hops (fused pull-gather, no atomics, no zero/scale passes)
    for (int k = 1; k <= KHOP; k++) {
        const float* hin = H + (size_t)(k - 1) * plane;
        float* hout      = H + (size_t)k * plane;
        spmm_pull<<<(N * 32 + 255) / 256, 256>>>(rowptr, col, nrm, hin, hout, N);
    }

    // 5) sigmoid-gated combine
    final_kernel<<<(N * 32 + 255) / 256, 256>>>(H, svec, out, N);
}

// round 3
// speedup vs baseline: 2.3503x; 1.6272x over previous
#include <cuda_runtime.h>
#include <cstdint>

#define NMAX   100000
#define EMAX   1600000
#define CDIM   50
#define HIDD   256
#define INDIM  500
#define KHOP   10

// ---------------- static scratch (no allocations allowed) ----------------
static __device__ float g_x1[(size_t)NMAX * HIDD];                 // MLP hidden
static __device__ float g_H [(size_t)(KHOP + 1) * NMAX * CDIM];    // hop results
static __device__ float g_norm[NMAX];
static __device__ int   g_deg   [NMAX];
static __device__ int   g_rowptr[NMAX + 1];
static __device__ int   g_cursor[NMAX];
static __device__ int   g_bsum  [1024];
static __device__ int   g_col   [EMAX];

// ================= TF32 tensor-core GEMM (3xTF32, fp32 accuracy) =================
// C = relu(A@B + bias). A:[M,K] row, B:[K,N] row, C:[M,N] row.
// Block tile 128x128x16, 256 threads = 8 warps (2x4), warp tile 64x32.

__device__ __forceinline__ void f2tf32(float x, uint32_t& hi, uint32_t& lo) {
    asm("cvt.rna.tf32.f32 %0, %1;" : "=r"(hi) : "f"(x));
    float r = x - __uint_as_float(hi);
    asm("cvt.rna.tf32.f32 %0, %1;" : "=r"(lo) : "f"(r));
}

__device__ __forceinline__ void mma_tf32(float* c, const uint32_t* a, const uint32_t* b) {
    asm volatile(
        "mma.sync.aligned.m16n8k8.row.col.f32.tf32.tf32.f32 "
        "{%0,%1,%2,%3}, {%4,%5,%6,%7}, {%8,%9}, {%0,%1,%2,%3};"
        : "+f"(c[0]), "+f"(c[1]), "+f"(c[2]), "+f"(c[3])
        : "r"(a[0]), "r"(a[1]), "r"(a[2]), "r"(a[3]), "r"(b[0]), "r"(b[1]));
}

#define TBM 128
#define TBN 128
#define TBK 16
#define TPAD 8

__global__ __launch_bounds__(256)
void gemm_tf32_relu(const float* __restrict__ A, const float* __restrict__ B,
                    const float* __restrict__ bias, float* __restrict__ C,
                    int M, int N, int K) {
    __shared__ uint32_t Ah[TBK][TBM + TPAD];
    __shared__ uint32_t Al[TBK][TBM + TPAD];
    __shared__ uint32_t Bh[TBK][TBN + TPAD];
    __shared__ uint32_t Bl[TBK][TBN + TPAD];

    const int tid  = threadIdx.x;
    const int lane = tid & 31;
    const int wid  = tid >> 5;
    const int wm   = (wid & 1) * 64;     // warp row offset within block tile
    const int wn   = (wid >> 1) * 32;    // warp col offset
    const int g    = lane >> 2;          // group id 0..7
    const int tg   = lane & 3;           // thread-in-group 0..3
    const int row0 = blockIdx.y * TBM;
    const int col0 = blockIdx.x * TBN;

    float acc[4][4][4];
#pragma unroll
    for (int i = 0; i < 4; i++)
#pragma unroll
        for (int j = 0; j < 4; j++)
#pragma unroll
            for (int q = 0; q < 4; q++) acc[i][j][q] = 0.f;

    const bool full_m = (row0 + TBM <= M);

    for (int kt = 0; kt < K; kt += TBK) {
        const bool full_k = (kt + TBK <= K);
        if (full_m && full_k) {
            // fast path: vectorized loads
#pragma unroll
            for (int it = tid; it < TBM * 4; it += 256) {       // A: 128 rows x 4 float4
                int r = it >> 2, c4 = (it & 3) * 4;
                float4 v = *reinterpret_cast<const float4*>(A + (size_t)(row0 + r) * K + kt + c4);
                uint32_t h, l;
                f2tf32(v.x, h, l); Ah[c4 + 0][r] = h; Al[c4 + 0][r] = l;
                f2tf32(v.y, h, l); Ah[c4 + 1][r] = h; Al[c4 + 1][r] = l;
                f2tf32(v.z, h, l); Ah[c4 + 2][r] = h; Al[c4 + 2][r] = l;
                f2tf32(v.w, h, l); Ah[c4 + 3][r] = h; Al[c4 + 3][r] = l;
            }
#pragma unroll
            for (int it = tid; it < TBK * (TBN / 4); it += 256) { // B: 16 rows x 32 float4
                int r = it >> 5, c4 = (it & 31) * 4;
                float4 v = *reinterpret_cast<const float4*>(B + (size_t)(kt + r) * N + col0 + c4);
                uint32_t h, l;
                f2tf32(v.x, h, l); Bh[r][c4 + 0] = h; Bl[r][c4 + 0] = l;
                f2tf32(v.y, h, l); Bh[r][c4 + 1] = h; Bl[r][c4 + 1] = l;
                f2tf32(v.z, h, l); Bh[r][c4 + 2] = h; Bl[r][c4 + 2] = l;
                f2tf32(v.w, h, l); Bh[r][c4 + 3] = h; Bl[r][c4 + 3] = l;
            }
        } else {
            // slow path: scalar loads with guards (tail K iter / last M block)
            for (int it = tid; it < TBM * TBK; it += 256) {
                int r = it / TBK, c = it % TBK;
                int gr = row0 + r, gk = kt + c;
                float x = (gr < M && gk < K) ? A[(size_t)gr * K + gk] : 0.f;
                uint32_t h, l; f2tf32(x, h, l);
                Ah[c][r] = h; Al[c][r] = l;
            }
            for (int it = tid; it < TBK * TBN; it += 256) {
                int r = it / TBN, c = it % TBN;
                int gk = kt + r, gc = col0 + c;
                float x = (gk < K && gc < N) ? B[(size_t)gk * N + gc] : 0.f;
                uint32_t h, l; f2tf32(x, h, l);
                Bh[r][c] = h; Bl[r][c] = l;
            }
        }
        __syncthreads();

#pragma unroll
        for (int ks = 0; ks < 2; ks++) {
            const int k0 = ks * 8;
            uint32_t ah[4][4], al[4][4], bh[4][2], bl[4][2];
#pragma unroll
            for (int mi = 0; mi < 4; mi++) {
                int m = wm + mi * 16;
                ah[mi][0] = Ah[k0 + tg    ][m + g    ];
                ah[mi][1] = Ah[k0 + tg    ][m + g + 8];
                ah[mi][2] = Ah[k0 + 4 + tg][m + g    ];
                ah[mi][3] = Ah[k0 + 4 + tg][m + g + 8];
                al[mi][0] = Al[k0 + tg    ][m + g    ];
                al[mi][1] = Al[k0 + tg    ][m + g + 8];
                al[mi][2] = Al[k0 + 4 + tg][m + g    ];
                al[mi][3] = Al[k0 + 4 + tg][m + g + 8];
            }
#pragma unroll
            for (int ni = 0; ni < 4; ni++) {
                int n = wn + ni * 8;
                bh[ni][0] = Bh[k0 + tg    ][n + g];
                bh[ni][1] = Bh[k0 + 4 + tg][n + g];
                bl[ni][0] = Bl[k0 + tg    ][n + g];
                bl[ni][1] = Bl[k0 + 4 + tg][n + g];
            }
#pragma unroll
            for (int mi = 0; mi < 4; mi++)
#pragma unroll
                for (int ni = 0; ni < 4; ni++) {
                    mma_tf32(acc[mi][ni], ah[mi], bh[ni]);  // hi*hi
                    mma_tf32(acc[mi][ni], al[mi], bh[ni]);  // lo*hi
                    mma_tf32(acc[mi][ni], ah[mi], bl[ni]);  // hi*lo
                }
        }
        __syncthreads();
    }

    // epilogue: bias + relu
#pragma unroll
    for (int mi = 0; mi < 4; mi++) {
#pragma unroll
        for (int ni = 0; ni < 4; ni++) {
            int c  = col0 + wn + ni * 8 + 2 * tg;
            float bv0 = bias[c], bv1 = bias[c + 1];
            int r0 = row0 + wm + mi * 16 + g;
            if (r0 < M) {
                float v0 = fmaxf(acc[mi][ni][0] + bv0, 0.f);
                float v1 = fmaxf(acc[mi][ni][1] + bv1, 0.f);
                *reinterpret_cast<float2*>(C + (size_t)r0 * N + c) = make_float2(v0, v1);
            }
            int r1 = r0 + 8;
            if (r1 < M) {
                float v2 = fmaxf(acc[mi][ni][2] + bv0, 0.f);
                float v3 = fmaxf(acc[mi][ni][3] + bv1, 0.f);
                *reinterpret_cast<float2*>(C + (size_t)r1 * N + c) = make_float2(v2, v3);
            }
        }
    }
}

// ---------------- fallback tiled fp32 GEMM (used for small GEMM2) ----------------
template <int BM, int BN, int BK, int TM, int TN, bool RELU>
__global__ void sgemm_bias(const float* __restrict__ A,
                           const float* __restrict__ B,
                           const float* __restrict__ bias,
                           float* __restrict__ C,
                           int M, int N, int K) {
    __shared__ float As[BK][BM];
    __shared__ float Bs[BK][BN];

    const int tid = threadIdx.x;
    const int tx  = tid % (BN / TN);
    const int ty  = tid / (BN / TN);
    const int row0 = blockIdx.y * BM;
    const int col0 = blockIdx.x * BN;

    float acc[TM][TN];
#pragma unroll
    for (int i = 0; i < TM; i++)
#pragma unroll
        for (int j = 0; j < TN; j++) acc[i][j] = 0.f;

    for (int kt = 0; kt < K; kt += BK) {
#pragma unroll 4
        for (int idx = tid; idx < BM * BK; idx += 256) {
            int m = idx / BK, k = idx % BK;
            int gr = row0 + m, gk = kt + k;
            As[k][m] = (gr < M && gk < K) ? A[(size_t)gr * K + gk] : 0.f;
        }
#pragma unroll 4
        for (int idx = tid; idx < BK * BN; idx += 256) {
            int k = idx / BN, n = idx % BN;
            int gk = kt + k, gc = col0 + n;
            Bs[k][n] = (gk < K && gc < N) ? B[(size_t)gk * N + gc] : 0.f;
        }
        __syncthreads();

#pragma unroll
        for (int kk = 0; kk < BK; kk++) {
            float aF[TM], bF[TN];
#pragma unroll
            for (int i = 0; i < TM; i++) aF[i] = As[kk][ty * TM + i];
#pragma unroll
            for (int j = 0; j < TN; j++) bF[j] = Bs[kk][tx * TN + j];
#pragma unroll
            for (int i = 0; i < TM; i++)
#pragma unroll
                for (int j = 0; j < TN; j++) acc[i][j] += aF[i] * bF[j];
        }
        __syncthreads();
    }

#pragma unroll
    for (int i = 0; i < TM; i++) {
        int gr = row0 + ty * TM + i;
        if (gr >= M) continue;
#pragma unroll
        for (int j = 0; j < TN; j++) {
            int gc = col0 + tx * TN + j;
            if (gc >= N) continue;
            float v = acc[i][j] + bias[gc];
            if (RELU) v = fmaxf(v, 0.f);
            C[(size_t)gr * N + gc] = v;
        }
    }
}

// ---------------- CSR build helpers ----------------
__global__ void zero_i_kernel(int* __restrict__ p, int n) {
    int i = blockIdx.x * blockDim.x + threadIdx.x;
    if (i < n) p[i] = 0;
}

__global__ void hist_kernel(const int* __restrict__ dst, int* __restrict__ deg, int E) {
    int i = blockIdx.x * blockDim.x + threadIdx.x;
    if (i < E) atomicAdd(&deg[dst[i]], 1);
}

__global__ void norm_kernel(const int* __restrict__ deg, float* __restrict__ nrm, int n) {
    int i = blockIdx.x * blockDim.x + threadIdx.x;
    if (i < n) nrm[i] = rsqrtf((float)deg[i]);
}

__global__ void scan_block(const int* __restrict__ deg, int* __restrict__ rowptr,
                           int* __restrict__ bsum, int n) {
    __shared__ int sh[512];
    int tid = threadIdx.x;
    int gid = blockIdx.x * 512 + tid;
    int v = (gid < n) ? deg[gid] : 0;
    sh[tid] = v;
    __syncthreads();
    for (int off = 1; off < 512; off <<= 1) {
        int t = (tid >= off) ? sh[tid - off] : 0;
        __syncthreads();
        sh[tid] += t;
        __syncthreads();
    }
    if (gid < n) rowptr[gid] = sh[tid] - v;
    if (tid == 511) bsum[blockIdx.x] = sh[511];
}

__global__ void scan_sums(int* __restrict__ bsum, int nb) {
    __shared__ int sh[1024];
    int tid = threadIdx.x;
    int v = (tid < nb) ? bsum[tid] : 0;
    sh[tid] = v;
    __syncthreads();
    for (int off = 1; off < 1024; off <<= 1) {
        int t = (tid >= off) ? sh[tid - off] : 0;
        __syncthreads();
        sh[tid] += t;
        __syncthreads();
    }
    if (tid < nb) bsum[tid] = sh[tid] - v;
}

__global__ void scan_finish(int* __restrict__ rowptr, const int* __restrict__ bsum,
                            int* __restrict__ cursor, int n, int E) {
    int gid = blockIdx.x * blockDim.x + threadIdx.x;
    if (gid < n) {
        int r = rowptr[gid] + bsum[gid / 512];
        rowptr[gid] = r;
        cursor[gid] = r;
    }
    if (gid == 0) rowptr[n] = E;
}

__global__ void fill_kernel(const int* __restrict__ src, const int* __restrict__ dst,
                            int* __restrict__ cursor, int* __restrict__ col, int E) {
    int e = blockIdx.x * blockDim.x + threadIdx.x;
    if (e >= E) return;
    int pos = atomicAdd(&cursor[dst[e]], 1);
    col[pos] = src[e];
}

// ---------------- fused pull-gather hop ----------------
__global__ void spmm_pull(const int* __restrict__ rowptr, const int* __restrict__ col,
                          const float* __restrict__ nrm,
                          const float* __restrict__ hin, float* __restrict__ hout,
                          int N) {
    int t = blockIdx.x * blockDim.x + threadIdx.x;
    int n = t >> 5;
    int lane = t & 31;
    if (n >= N) return;

    int beg = rowptr[n];
    int end = rowptr[n + 1];
    const bool hi = (lane < CDIM - 32);

    float acc0 = 0.f, acc1 = 0.f;
    int j = beg;
    for (; j + 1 < end; j += 2) {
        int s0 = col[j], s1 = col[j + 1];
        float n0 = nrm[s0], n1 = nrm[s1];
        const float* r0 = hin + (size_t)s0 * CDIM;
        const float* r1 = hin + (size_t)s1 * CDIM;
        float a0 = r0[lane];
        float a1 = r1[lane];
        float b0 = hi ? r0[lane + 32] : 0.f;
        float b1 = hi ? r1[lane + 32] : 0.f;
        acc0 += n0 * a0 + n1 * a1;
        acc1 += n0 * b0 + n1 * b1;
    }
    if (j < end) {
        int s0 = col[j];
        float n0 = nrm[s0];
        const float* r0 = hin + (size_t)s0 * CDIM;
        acc0 += n0 * r0[lane];
        if (hi) acc1 += n0 * r0[lane + 32];
    }

    float nd = nrm[n];
    hout[(size_t)n * CDIM + lane] = nd * acc0;
    if (hi) hout[(size_t)n * CDIM + lane + 32] = nd * acc1;
}

// ---------------- final sigmoid-gated combine ----------------
__global__ void final_kernel(const float* __restrict__ H, const float* __restrict__ s,
                             float* __restrict__ out, int N) {
    int t = blockIdx.x * blockDim.x + threadIdx.x;
    int n = t >> 5;
    int lane = t & 31;
    if (n >= N) return;

    const bool hi = (lane < CDIM - 32);
    float s0 = s[lane];
    float s1 = hi ? s[lane + 32] : 0.f;

    float acc0 = 0.f, acc1 = 0.f;
    size_t plane = (size_t)N * CDIM;
    const float* base = H + (size_t)n * CDIM;

#pragma unroll
    for (int k = 0; k <= KHOP; k++) {
        const float* r = base + (size_t)k * plane;
        float h0 = r[lane];
        float h1 = hi ? r[lane + 32] : 0.f;
        float dot = h0 * s0 + h1 * s1;
#pragma unroll
        for (int off = 16; off; off >>= 1)
            dot += __shfl_xor_sync(0xffffffffu, dot, off);
        float S = 1.f / (1.f + __expf(-dot));
        acc0 += S * h0;
        acc1 += S * h1;
    }
    out[(size_t)n * CDIM + lane] = acc0;
    if (hi) out[(size_t)n * CDIM + lane + 32] = acc1;
}

// ---------------- launch ----------------
extern "C" void kernel_launch(void* const* d_in, const int* in_sizes, int n_in,
                              void* d_out, int out_size) {
    const float* feats = (const float*)d_in[0];   // [N, 500]
    const float* W1    = (const float*)d_in[1];   // [500, 256]
    const float* b1    = (const float*)d_in[2];   // [256]
    const float* W2    = (const float*)d_in[3];   // [256, 50]
    const float* b2    = (const float*)d_in[4];   // [50]
    const float* svec  = (const float*)d_in[5];   // [50, 1]
    const int*   src   = (const int*)d_in[6];     // [E]
    const int*   dst   = (const int*)d_in[7];     // [E]
    float* out = (float*)d_out;

    const int N = in_sizes[0] / INDIM;            // 100000
    const int E = in_sizes[6];                    // 1600000

    void *pv;
    cudaGetSymbolAddress(&pv, g_x1);     float* x1     = (float*)pv;
    cudaGetSymbolAddress(&pv, g_H);      float* H      = (float*)pv;
    cudaGetSymbolAddress(&pv, g_norm);   float* nrm    = (float*)pv;
    cudaGetSymbolAddress(&pv, g_deg);    int*   deg    = (int*)pv;
    cudaGetSymbolAddress(&pv, g_rowptr); int*   rowptr = (int*)pv;
    cudaGetSymbolAddress(&pv, g_cursor); int*   cursor = (int*)pv;
    cudaGetSymbolAddress(&pv, g_bsum);   int*   bsum   = (int*)pv;
    cudaGetSymbolAddress(&pv, g_col);    int*   col    = (int*)pv;

    const size_t plane = (size_t)N * CDIM;
    const int nb = (N + 511) / 512;

    // 1) MLP layer 1 on tensor cores: x1 = relu(feats @ W1 + b1), 3xTF32
    {
        dim3 grid(HIDD / TBN, (N + TBM - 1) / TBM);   // (2, 782)
        gemm_tf32_relu<<<grid, 256>>>(feats, W1, b1, x1, N, HIDD, INDIM);
    }
    // 2) MLP layer 2: H[0] = x1 @ W2 + b2 (small, SIMT)
    {
        dim3 grid((CDIM + 63) / 64, (N + 127) / 128);
        sgemm_bias<128, 64, 16, 8, 4, false><<<grid, 256>>>(x1, W2, b2, H, N, CDIM, HIDD);
    }
    // 3) CSR build
    zero_i_kernel<<<(N + 255) / 256, 256>>>(deg, N);
    hist_kernel<<<(E + 255) / 256, 256>>>(dst, deg, E);
    norm_kernel<<<(N + 255) / 256, 256>>>(deg, nrm, N);
    scan_block<<<nb, 512>>>(deg, rowptr, bsum, N);
    scan_sums<<<1, 1024>>>(bsum, nb);
    scan_finish<<<(N + 255) / 256, 256>>>(rowptr, bsum, cursor, N, E);
    fill_kernel<<<(E + 255) / 256, 256>>>(src, dst, cursor, col, E);

    // 4) K propagation hops
    for (int k = 1; k <= KHOP; k++) {
        const float* hin = H + (size_t)(k - 1) * plane;
        float* hout      = H + (size_t)k * plane;
        spmm_pull<<<(N * 32 + 255) / 256, 256>>>(rowptr, col, nrm, hin, hout, N);
    }

    // 5) sigmoid-gated combine
    final_kernel<<<(N * 32 + 255) / 256, 256>>>(H, svec, out, N);
}